// round 15
// baseline (speedup 1.0000x reference)
#include <cuda_runtime.h>
#include <cuda_fp16.h>
#include <cstdint>

// Problem constants
constexpr int C   = 64;
constexpr int H   = 128;
constexpr int W   = 128;
constexpr int HW  = 16384;
constexpr int B   = 8;
constexpr int C3  = 192;

// ---------------------------------------------------------------------------
// Scratch (device globals). Attention intermediates split fp16 (hi + lo);
// conv operands are plain fp16 (validated error model: rel_err ~3e-4).
// ---------------------------------------------------------------------------
__device__ __half g_x1h[(size_t)B * H * C * W], g_x1l[(size_t)B * H * C * W];
__device__ __half g_x2h[(size_t)B * H * C * W], g_x2l[(size_t)B * H * C * W];
__device__ __half g_xfh[(size_t)B * H * C * W], g_xfl[(size_t)B * H * C * W];
__device__ __half g_xrh[(size_t)B * H * C * W], g_xrl[(size_t)B * H * C * W];
__device__ __half g_xpth[(size_t)B * H * W * C], g_xptl[(size_t)B * H * W * C];
__device__ __half g_inh[(size_t)B * H * W * C3];
__device__ __half g_wh16[54 * 192 * 32];

// ---------------------------------------------------------------------------
// Helpers
// ---------------------------------------------------------------------------
__device__ __forceinline__ void cpa16(void* dst, const void* src) {
    uint32_t d = (uint32_t)__cvta_generic_to_shared(dst);
    asm volatile("cp.async.cg.shared.global [%0], [%1], 16;" :: "r"(d), "l"(src));
}
#define CP_COMMIT() asm volatile("cp.async.commit_group;" ::: "memory")
#define CP_WAIT2()  asm volatile("cp.async.wait_group 2;" ::: "memory")

__device__ __forceinline__ void mma16816(float acc[4], uint32_t a0, uint32_t a1,
                                         uint32_t a2, uint32_t a3,
                                         uint32_t b0, uint32_t b1) {
    asm volatile(
        "mma.sync.aligned.m16n8k16.row.col.f32.f16.f16.f32 "
        "{%0,%1,%2,%3}, {%4,%5,%6,%7}, {%8,%9}, {%0,%1,%2,%3};"
        : "+f"(acc[0]), "+f"(acc[1]), "+f"(acc[2]), "+f"(acc[3])
        : "r"(a0), "r"(a1), "r"(a2), "r"(a3), "r"(b0), "r"(b1));
}

__device__ __forceinline__ void ldsm4(uint32_t& r0, uint32_t& r1, uint32_t& r2,
                                      uint32_t& r3, const __half* p) {
    uint32_t a = (uint32_t)__cvta_generic_to_shared(p);
    asm volatile("ldmatrix.sync.aligned.m8n8.x4.shared.b16 {%0,%1,%2,%3}, [%4];"
                 : "=r"(r0), "=r"(r1), "=r"(r2), "=r"(r3) : "r"(a));
}

__device__ __forceinline__ void split16(float v, __half& hi, __half& lo) {
    hi = __float2half_rn(v);
    lo = __float2half_rn(v - __half2float(hi));
}

// ---------------------------------------------------------------------------
// Kernel 1: tensor-core pointwise projections (3-term fp16 split).
// ---------------------------------------------------------------------------

#define PJS 72
#define PO_WH  0
#define PO_WL  4608
#define PO_INH 9216
#define PO_INL 18432
#define PO_TMP 27648            // fp32 [64][129] staging (16512 halfs)
#define PROJ_SMEM_HALFS (27648 + 16512)

__global__ __launch_bounds__(256, 2) void proj_mma_kernel(
    const float* __restrict__ x, const float* __restrict__ xf, const float* __restrict__ xr,
    const float* __restrict__ Wx,  const float* __restrict__ bx,
    const float* __restrict__ Wx1, const float* __restrict__ bx1,
    const float* __restrict__ Wx2, const float* __restrict__ bx2,
    const float* __restrict__ Wxf, const float* __restrict__ bxf,
    const float* __restrict__ Wxr, const float* __restrict__ bxr) {
    extern __shared__ __align__(16) __half smh[];
    __half* sWh  = smh + PO_WH;
    __half* sWl  = smh + PO_WL;
    __half* sInH = smh + PO_INH;
    __half* sInL = smh + PO_INL;
    float*  sTmp = (float*)(smh + PO_TMP);   // [64][129]

    const int tid = threadIdx.x;
    const int b   = blockIdx.x >> 7;
    const int h   = blockIdx.x & 127;
    const size_t bh = (size_t)b * 128 + h;
    const size_t gbase = (size_t)b * C * HW + (size_t)h * W;

    const int lane = tid & 31;
    const int wid = tid >> 5;
    const int lr = lane >> 2;
    const int lc2 = (lane & 3) * 2;
    const int grp = lane >> 3;
    const int gr  = lane & 7;
    const int aoffW = ((grp & 1) * 8 + gr) * PJS + (grp >> 1) * 8;
    const int boffI = ((grp >> 1) * 8 + gr) * PJS + (grp & 1) * 8;
    const int m0 = (wid & 1) * 32;
    const int n0 = (wid >> 1) * 32;

    auto loadW = [&](const float* Wg) {
        for (int i = tid; i < 4096; i += 256) {
            int o = i >> 6, c = i & 63;
            __half hi, lo;
            split16(Wg[i], hi, lo);
            sWh[o * PJS + c] = hi;
            sWl[o * PJS + c] = lo;
        }
    };
    auto loadTmp = [&](const float* src) {
        for (int i = tid; i < 8192; i += 256) {
            int c = i >> 7, p = i & 127;
            sTmp[c * 129 + p] = src[gbase + (size_t)c * HW + p];
        }
    };
    auto transSplit = [&]() {
        for (int i = tid; i < 8192; i += 256) {
            int c = i & 63, w = i >> 6;
            __half hi, lo;
            split16(sTmp[c * 129 + w], hi, lo);
            sInH[w * PJS + c] = hi;
            sInL[w * PJS + c] = lo;
        }
    };

    float acc[2][4][4];
    auto gemm3 = [&]() {
#pragma unroll
        for (int mt = 0; mt < 2; mt++)
#pragma unroll
            for (int nf = 0; nf < 4; nf++)
#pragma unroll
                for (int i = 0; i < 4; i++) acc[mt][nf][i] = 0.f;
#pragma unroll
        for (int ks = 0; ks < 4; ks++) {
            const int k0 = ks * 16;
            uint32_t bhf[4][2], blf[4][2];
#pragma unroll
            for (int ntp = 0; ntp < 2; ntp++) {
                const int nb = (n0 + ntp * 16) * PJS + k0 + boffI;
                ldsm4(bhf[ntp * 2][0], bhf[ntp * 2][1], bhf[ntp * 2 + 1][0],
                      bhf[ntp * 2 + 1][1], sInH + nb);
                ldsm4(blf[ntp * 2][0], blf[ntp * 2][1], blf[ntp * 2 + 1][0],
                      blf[ntp * 2 + 1][1], sInL + nb);
            }
#pragma unroll
            for (int mt = 0; mt < 2; mt++) {
                const int mb = (m0 + mt * 16) * PJS + k0 + aoffW;
                uint32_t ah0, ah1, ah2, ah3, al0, al1, al2, al3;
                ldsm4(ah0, ah1, ah2, ah3, sWh + mb);
                ldsm4(al0, al1, al2, al3, sWl + mb);
#pragma unroll
                for (int nf = 0; nf < 4; nf++)
                    mma16816(acc[mt][nf], ah0, ah1, ah2, ah3, bhf[nf][0], bhf[nf][1]);
#pragma unroll
                for (int nf = 0; nf < 4; nf++)
                    mma16816(acc[mt][nf], al0, al1, al2, al3, bhf[nf][0], bhf[nf][1]);
#pragma unroll
                for (int nf = 0; nf < 4; nf++)
                    mma16816(acc[mt][nf], ah0, ah1, ah2, ah3, blf[nf][0], blf[nf][1]);
            }
        }
    };

    auto storeCW = [&](const float* bias, __half* dh, __half* dl) {
#pragma unroll
        for (int mt = 0; mt < 2; mt++) {
            const int ob = m0 + mt * 16 + lr;
            const float b0 = __ldg(bias + ob);
            const float b1 = __ldg(bias + ob + 8);
#pragma unroll
            for (int nf = 0; nf < 4; nf++) {
                const int wcol = n0 + nf * 8 + lc2;
                __half h0, l0, h1, l1;
                split16(acc[mt][nf][0] + b0, h0, l0);
                split16(acc[mt][nf][1] + b0, h1, l1);
                size_t rb = (bh * 64 + ob) * 128 + wcol;
                *(__half2*)(dh + rb) = __halves2half2(h0, h1);
                *(__half2*)(dl + rb) = __halves2half2(l0, l1);
                split16(acc[mt][nf][2] + b1, h0, l0);
                split16(acc[mt][nf][3] + b1, h1, l1);
                rb += (size_t)8 * 128;
                *(__half2*)(dh + rb) = __halves2half2(h0, h1);
                *(__half2*)(dl + rb) = __halves2half2(l0, l1);
            }
        }
    };

    // ---- xp chain ----
    loadTmp(x);
    __syncthreads();
    transSplit();
    loadW(Wx);
    __syncthreads();
    gemm3();
    __syncthreads();
    {
#pragma unroll
        for (int mt = 0; mt < 2; mt++) {
            const int ob = m0 + mt * 16 + lr;
            const float b0 = __ldg(bx + ob);
            const float b1 = __ldg(bx + ob + 8);
#pragma unroll
            for (int nf = 0; nf < 4; nf++) {
#pragma unroll
                for (int i = 0; i < 4; i++) {
                    int o = ob + ((i & 2) ? 8 : 0);
                    int w = n0 + nf * 8 + lc2 + (i & 1);
                    __half hi, lo;
                    split16(acc[mt][nf][i] + ((i & 2) ? b1 : b0), hi, lo);
                    sInH[w * PJS + o] = hi;
                    sInL[w * PJS + o] = lo;
                }
            }
        }
    }
    loadW(Wx1);
    __syncthreads();
    {
        __half* gh = g_xpth + bh * 128 * 64;
        __half* gl = g_xptl + bh * 128 * 64;
        for (int i = tid; i < 1024; i += 256) {
            int r = i >> 3, g = i & 7;
            *(uint4*)(gh + r * 64 + g * 8) = *(const uint4*)(sInH + r * PJS + g * 8);
            *(uint4*)(gl + r * 64 + g * 8) = *(const uint4*)(sInL + r * PJS + g * 8);
        }
    }
    gemm3();
    storeCW(bx1, g_x1h, g_x1l);
    __syncthreads();
    loadW(Wx2);
    loadTmp(xf);
    __syncthreads();
    gemm3();
    storeCW(bx2, g_x2h, g_x2l);
    __syncthreads();
    transSplit();
    loadW(Wxf);
    __syncthreads();
    gemm3();
    storeCW(bxf, g_xfh, g_xfl);
    loadTmp(xr);
    __syncthreads();
    transSplit();
    loadW(Wxr);
    __syncthreads();
    gemm3();
    storeCW(bxr, g_xrh, g_xrl);
}

// ---------------------------------------------------------------------------
// Kernel 2: tensor-core attention + conv-input packing (unchanged).
// ---------------------------------------------------------------------------

#define AS1 136
#define ASP 72
#define ASS 72
#define ASF 129
#define O_X1H 0
#define O_X1L 8704
#define O_XFH 17408
#define O_XFL 26112
#define O_PH  34816
#define O_PL  44032
#define ATTN_SMEM_HALFS 53248   // 106496 bytes

__global__ __launch_bounds__(256, 2) void attn_mma_kernel(const float* __restrict__ x) {
    extern __shared__ __align__(16) __half smh[];
    __half* sX1h = smh + O_X1H;
    __half* sX1l = smh + O_X1L;
    __half* sXfh = smh + O_XFH;
    __half* sXfl = smh + O_XFL;
    __half* sPh  = smh + O_PH;
    __half* sPl  = smh + O_PL;
    __half* sSh  = smh + O_XFH;            // alias over sXf after GEMM1
    __half* sSl  = smh + O_XFH + 4608;
    float*  sF   = (float*)smh;            // alias over sX1 (8256 floats)

    const int tid = threadIdx.x;
    const int h = blockIdx.x, b = blockIdx.y;
    const size_t bh = (size_t)b * 128 + h;

    const int lane = tid & 31;
    const int wid = tid >> 5;
    const int lr = lane >> 2;
    const int lc2 = (lane & 3) * 2;
    const int grp = lane >> 3;
    const int gr  = lane & 7;

    uint32_t* outh = (uint32_t*)g_inh;
    const size_t wbase = bh * 128 * 96;

    {
        const __half* srcH = g_xpth + bh * 128 * 64;
        const __half* srcL = g_xptl + bh * 128 * 64;
        for (int idx = tid; idx < 1024; idx += 256) {
            int r = idx >> 3, g = idx & 7;
            *(uint4*)(sPh + r * ASP + g * 8) = *(const uint4*)(srcH + r * 64 + g * 8);
            *(uint4*)(sPl + r * ASP + g * 8) = *(const uint4*)(srcL + r * 64 + g * 8);
        }
    }
    {
        const size_t xbase = (size_t)b * C * HW + (size_t)h * W;
        for (int idx = tid; idx < 8192; idx += 256) {
            int c = idx >> 7, w = idx & 127;
            sF[c * ASF + w] = x[xbase + (size_t)c * HW + w];
        }
        __syncthreads();
        for (int idx = tid; idx < 4096; idx += 256) {
            int q = idx & 31, w = idx >> 5;
            int c = q * 2;
            __half2 ph = __halves2half2(__float2half_rn(sF[c * ASF + w]),
                                        __float2half_rn(sF[(c + 1) * ASF + w]));
            outh[wbase + (size_t)w * 96 + 64 + q] = *(uint32_t*)&ph;
        }
    }

    const int aoff1 = ((grp & 1) * 8 + gr) * AS1 + (grp >> 1) * 8;
    const int boff1 = ((grp >> 1) * 8 + gr) * AS1 + (grp & 1) * 8;
    const int aoffS = ((grp & 1) * 8 + gr) * ASS + (grp >> 1) * 8;
    const int boffP = ((grp >> 1) * 8 + gr) * ASP + (grp & 1) * 8;

    for (int pass = 0; pass < 2; pass++) {
        const __half* gAh = pass ? g_x2h : g_x1h;
        const __half* gAl = pass ? g_x2l : g_x1l;
        const __half* gBh = pass ? g_xrh : g_xfh;
        const __half* gBl = pass ? g_xrl : g_xfl;

        __syncthreads();
        {
            const size_t sb = bh * 64 * 128;
            for (int idx = tid; idx < 1024; idx += 256) {
                int r = idx >> 4, g = idx & 15;
                *(uint4*)(sX1h + r * AS1 + g * 8) = *(const uint4*)(gAh + sb + r * 128 + g * 8);
                *(uint4*)(sX1l + r * AS1 + g * 8) = *(const uint4*)(gAl + sb + r * 128 + g * 8);
                *(uint4*)(sXfh + r * AS1 + g * 8) = *(const uint4*)(gBh + sb + r * 128 + g * 8);
                *(uint4*)(sXfl + r * AS1 + g * 8) = *(const uint4*)(gBl + sb + r * 128 + g * 8);
            }
        }
        __syncthreads();

        float sacc[4][4];
#pragma unroll
        for (int nf = 0; nf < 4; nf++)
#pragma unroll
            for (int i = 0; i < 4; i++) sacc[nf][i] = 0.f;
        {
            const int m0 = (wid & 3) * 16, n0 = (wid >> 2) * 32;
#pragma unroll
            for (int ks = 0; ks < 8; ks++) {
                const int k0 = ks * 16;
                uint32_t bhf[4][2], blf[4][2];
#pragma unroll
                for (int ntp = 0; ntp < 2; ntp++) {
                    const int nb = (n0 + ntp * 16) * AS1 + k0 + boff1;
                    ldsm4(bhf[ntp * 2][0], bhf[ntp * 2][1], bhf[ntp * 2 + 1][0],
                          bhf[ntp * 2 + 1][1], sXfh + nb);
                    ldsm4(blf[ntp * 2][0], blf[ntp * 2][1], blf[ntp * 2 + 1][0],
                          blf[ntp * 2 + 1][1], sXfl + nb);
                }
                const int mb = m0 * AS1 + k0 + aoff1;
                uint32_t ah0, ah1, ah2, ah3, al0, al1, al2, al3;
                ldsm4(ah0, ah1, ah2, ah3, sX1h + mb);
                ldsm4(al0, al1, al2, al3, sX1l + mb);
#pragma unroll
                for (int nf = 0; nf < 4; nf++)
                    mma16816(sacc[nf], ah0, ah1, ah2, ah3, bhf[nf][0], bhf[nf][1]);
#pragma unroll
                for (int nf = 0; nf < 4; nf++)
                    mma16816(sacc[nf], al0, al1, al2, al3, bhf[nf][0], bhf[nf][1]);
#pragma unroll
                for (int nf = 0; nf < 4; nf++)
                    mma16816(sacc[nf], ah0, ah1, ah2, ah3, blf[nf][0], blf[nf][1]);
            }
        }
        __syncthreads();

        {
            const int m0 = (wid & 3) * 16, n0 = (wid >> 2) * 32;
#pragma unroll
            for (int nf = 0; nf < 4; nf++)
#pragma unroll
                for (int i = 0; i < 4; i++) {
                    int row = m0 + lr + (i >= 2 ? 8 : 0);
                    int col = n0 + nf * 8 + lc2 + (i & 1);
                    __half hi, lo;
                    split16(sacc[nf][i], hi, lo);
                    sSh[row * ASS + col] = hi;
                    sSl[row * ASS + col] = lo;
                }
        }
        __syncthreads();

        float facc[2][4][4];
#pragma unroll
        for (int mt = 0; mt < 2; mt++)
#pragma unroll
            for (int nf = 0; nf < 4; nf++)
#pragma unroll
                for (int i = 0; i < 4; i++) facc[mt][nf][i] = 0.f;
        {
            const int m0 = (wid & 1) * 32, n0 = (wid >> 1) * 32;
#pragma unroll
            for (int ks = 0; ks < 4; ks++) {
                const int k0 = ks * 16;
                uint32_t bhf[4][2], blf[4][2];
#pragma unroll
                for (int ntp = 0; ntp < 2; ntp++) {
                    const int nb = (n0 + ntp * 16) * ASP + k0 + boffP;
                    ldsm4(bhf[ntp * 2][0], bhf[ntp * 2][1], bhf[ntp * 2 + 1][0],
                          bhf[ntp * 2 + 1][1], sPh + nb);
                    ldsm4(blf[ntp * 2][0], blf[ntp * 2][1], blf[ntp * 2 + 1][0],
                          blf[ntp * 2 + 1][1], sPl + nb);
                }
#pragma unroll
                for (int mt = 0; mt < 2; mt++) {
                    const int mb = (m0 + mt * 16) * ASS + k0 + aoffS;
                    uint32_t ah0, ah1, ah2, ah3, al0, al1, al2, al3;
                    ldsm4(ah0, ah1, ah2, ah3, sSh + mb);
                    ldsm4(al0, al1, al2, al3, sSl + mb);
#pragma unroll
                    for (int nf = 0; nf < 4; nf++)
                        mma16816(facc[mt][nf], ah0, ah1, ah2, ah3, bhf[nf][0], bhf[nf][1]);
#pragma unroll
                    for (int nf = 0; nf < 4; nf++)
                        mma16816(facc[mt][nf], al0, al1, al2, al3, bhf[nf][0], bhf[nf][1]);
#pragma unroll
                    for (int nf = 0; nf < 4; nf++)
                        mma16816(facc[mt][nf], ah0, ah1, ah2, ah3, blf[nf][0], blf[nf][1]);
                }
            }
        }
        {
            const int m0 = (wid & 1) * 32, n0 = (wid >> 1) * 32;
#pragma unroll
            for (int mt = 0; mt < 2; mt++)
#pragma unroll
                for (int nf = 0; nf < 4; nf++)
#pragma unroll
                    for (int i = 0; i < 4; i++) {
                        int row = m0 + mt * 16 + lr + (i >= 2 ? 8 : 0);
                        int col = n0 + nf * 8 + lc2 + (i & 1);
                        sF[row * ASF + col] = facc[mt][nf][i];
                    }
        }
        __syncthreads();

        for (int idx = tid; idx < 4096; idx += 256) {
            int q = idx & 31, w = idx >> 5;
            int c = q * 2;
            __half2 ph = __halves2half2(__float2half_rn(sF[c * ASF + w]),
                                        __float2half_rn(sF[(c + 1) * ASF + w]));
            outh[wbase + (size_t)w * 96 + pass * 32 + q] = *(uint32_t*)&ph;
        }
    }
}

// ---------------------------------------------------------------------------
// Kernel 3a: weight prep (fp16).
// ---------------------------------------------------------------------------
__global__ void wprep_kernel(const float* __restrict__ Wm) {
    const int kc = blockIdx.x;       // 0..53
    const int o  = threadIdx.x;      // 0..191
    const int tap = kc / 6;
    const int ch0 = (kc - tap * 6) * 32;
#pragma unroll
    for (int j = 0; j < 32; j++) {
        float v  = Wm[((size_t)o * 192 + ch0 + j) * 9 + tap];
        g_wh16[((size_t)kc * 192 + o) * 32 + j] = __float2half_rn(v);
    }
}

// ---------------------------------------------------------------------------
// Kernel 3b: pure fp16 mma.sync implicit-GEMM conv + BN + ReLU.
// CTA tile 96(o) x 128(w); blockIdx.z selects the o-half. 3 CTAs/SM.
// 4-stage cp.async pipeline, one sync per K-chunk.
// ---------------------------------------------------------------------------

#define AST 40
#define A_TILE (96 * AST)            // 3840 halfs
#define B_TILE (128 * AST)           // 5120 halfs
#define CONV_SMEM_BYTES ((4 * A_TILE + 4 * B_TILE) * 2 + 384 * 4)

__global__ __launch_bounds__(256, 3) void conv_mma_kernel(
    const float* __restrict__ bm, const float* __restrict__ gamma,
    const float* __restrict__ beta, const float* __restrict__ mean,
    const float* __restrict__ var, float* __restrict__ out) {
    extern __shared__ __align__(16) __half smh[];
    __half* sAh = smh;                        // [4][A_TILE]
    __half* sBh = sAh + 4 * A_TILE;           // [4][B_TILE]
    float* ssc = (float*)(sBh + 4 * B_TILE);
    float* sbi = ssc + 192;

    const int tid = threadIdx.x;
    const int h = blockIdx.x, b = blockIdx.y;
    const int oc = blockIdx.z;                // 0/1: which 96 out-channels
    const int obase = oc * 96;

    if (tid < 96) {
        int o = obase + tid;
        float scv = gamma[o] * rsqrtf(var[o] + 1e-4f);
        ssc[tid] = scv;
        sbi[tid] = (bm[o] - mean[o]) * scv + beta[o];
    }

    const int lane = tid & 31;
    const int wid = tid >> 5;
    const int wm = wid & 1;          // 2 M-groups of 48
    const int wn = wid >> 1;         // 4 N-groups of 32
    const int lr = lane >> 2;
    const int lc2 = (lane & 3) * 2;
    const int grp = lane >> 3;
    const int gr  = lane & 7;
    const int aoff = ((grp & 1) * 8 + gr) * AST + (grp >> 1) * 8;
    const int boff = ((grp >> 1) * 8 + gr) * AST + (grp & 1) * 8;

    float acc[3][4][4];
#pragma unroll
    for (int mt = 0; mt < 3; mt++)
#pragma unroll
        for (int nt = 0; nt < 4; nt++)
#pragma unroll
            for (int i = 0; i < 4; i++) acc[mt][nt][i] = 0.f;

    auto stage = [&](int kc, int buf) {
        const int tap = kc / 6;
        const int ch0 = (kc - tap * 6) * 32;
        const int dh = tap / 3 - 1;
        const int dw = tap - (tap / 3) * 3 - 1;
        const int row = h + dh;
        const bool rok = ((unsigned)row < 128u);
        const __half* wh = g_wh16 + (size_t)kc * 6144 + (size_t)obase * 32;
        // A: 96 rows x 4 granules = 384
        {
            int idx = tid;                    // 0..255
            int r = idx >> 2, g = idx & 3;
            cpa16(sAh + buf * A_TILE + r * AST + g * 8, wh + r * 32 + g * 8);
            idx = tid + 256;
            if (idx < 384) {
                r = idx >> 2; g = idx & 3;
                cpa16(sAh + buf * A_TILE + r * AST + g * 8, wh + r * 32 + g * 8);
            }
        }
        const size_t rowbase = ((size_t)(b * 128 + row) * 128) * 192;
#pragma unroll
        for (int i = 0; i < 2; i++) {
            int idx = tid + i * 256;
            int r = idx >> 2, g = idx & 3;
            int wsrc = r + dw;
            bool ok = rok && ((unsigned)wsrc < 128u);
            __half* dh_ = sBh + buf * B_TILE + r * AST + g * 8;
            if (ok) {
                cpa16(dh_, g_inh + rowbase + (size_t)wsrc * 192 + ch0 + g * 8);
            } else {
                *(uint4*)dh_ = make_uint4(0, 0, 0, 0);
            }
        }
    };

    stage(0, 0); CP_COMMIT();
    stage(1, 1); CP_COMMIT();
    stage(2, 2); CP_COMMIT();

    for (int kc = 0; kc < 54; kc++) {
        const int buf = kc & 3;
        CP_WAIT2();
        __syncthreads();
        if (kc + 3 < 54) stage(kc + 3, (kc + 3) & 3);
        CP_COMMIT();

        const __half* bAh = sAh + buf * A_TILE;
        const __half* bBh = sBh + buf * B_TILE;

#pragma unroll
        for (int ks = 0; ks < 2; ks++) {
            const int kk = ks * 16;
            uint32_t bh[4][2];
#pragma unroll
            for (int ntp = 0; ntp < 2; ntp++) {
                const int nb = (wn * 32 + ntp * 16) * AST + kk + boff;
                ldsm4(bh[ntp * 2][0], bh[ntp * 2][1], bh[ntp * 2 + 1][0],
                      bh[ntp * 2 + 1][1], bBh + nb);
            }
#pragma unroll
            for (int mt = 0; mt < 3; mt++) {
                const int mb = (wm * 48 + mt * 16) * AST + kk + aoff;
                uint32_t ah0, ah1, ah2, ah3;
                ldsm4(ah0, ah1, ah2, ah3, bAh + mb);
#pragma unroll
                for (int nt = 0; nt < 4; nt++)
                    mma16816(acc[mt][nt], ah0, ah1, ah2, ah3, bh[nt][0], bh[nt][1]);
            }
        }
    }

#pragma unroll
    for (int mt = 0; mt < 3; mt++) {
        int ol = wm * 48 + mt * 16 + lr;      // local o in [0,96)
        float s0 = ssc[ol],     bi0 = sbi[ol];
        float s1 = ssc[ol + 8], bi1 = sbi[ol + 8];
#pragma unroll
        for (int nt = 0; nt < 4; nt++) {
            int wcol = wn * 32 + nt * 8 + lc2;
            float2 v0, v1;
            v0.x = fmaxf(acc[mt][nt][0] * s0 + bi0, 0.f);
            v0.y = fmaxf(acc[mt][nt][1] * s0 + bi0, 0.f);
            v1.x = fmaxf(acc[mt][nt][2] * s1 + bi1, 0.f);
            v1.y = fmaxf(acc[mt][nt][3] * s1 + bi1, 0.f);
            size_t p0 = (((size_t)b * C3 + obase + ol)     * H + h) * W + wcol;
            size_t p1 = (((size_t)b * C3 + obase + ol + 8) * H + h) * W + wcol;
            *(float2*)(out + p0) = v0;
            *(float2*)(out + p1) = v1;
        }
    }
}

// ---------------------------------------------------------------------------

extern "C" void kernel_launch(void* const* d_in, const int* in_sizes, int n_in,
                              void* d_out, int out_size) {
    const float* x    = (const float*)d_in[0];
    const float* xf   = (const float*)d_in[1];
    const float* xr   = (const float*)d_in[2];
    const float* Wx   = (const float*)d_in[3];
    const float* bx   = (const float*)d_in[4];
    const float* Wx1  = (const float*)d_in[5];
    const float* bx1  = (const float*)d_in[6];
    const float* Wx2  = (const float*)d_in[7];
    const float* bx2  = (const float*)d_in[8];
    const float* Wxf  = (const float*)d_in[9];
    const float* bxf  = (const float*)d_in[10];
    const float* Wxr  = (const float*)d_in[11];
    const float* bxr  = (const float*)d_in[12];
    const float* Wm   = (const float*)d_in[13];
    const float* bm   = (const float*)d_in[14];
    const float* gam  = (const float*)d_in[15];
    const float* bet  = (const float*)d_in[16];
    const float* mean = (const float*)d_in[17];
    const float* var  = (const float*)d_in[18];
    float* out = (float*)d_out;

    const int proj_smem = PROJ_SMEM_HALFS * 2;
    const int attn_smem = ATTN_SMEM_HALFS * 2;
    const int conv_smem = CONV_SMEM_BYTES;
    cudaFuncSetAttribute(proj_mma_kernel, cudaFuncAttributeMaxDynamicSharedMemorySize, proj_smem);
    cudaFuncSetAttribute(attn_mma_kernel, cudaFuncAttributeMaxDynamicSharedMemorySize, attn_smem);
    cudaFuncSetAttribute(conv_mma_kernel, cudaFuncAttributeMaxDynamicSharedMemorySize, conv_smem);

    proj_mma_kernel<<<B * H, 256, proj_smem>>>(x, xf, xr, Wx, bx, Wx1, bx1,
                                               Wx2, bx2, Wxf, bxf, Wxr, bxr);
    wprep_kernel<<<54, 192>>>(Wm);
    attn_mma_kernel<<<dim3(H, B), 256, attn_smem>>>(x);
    conv_mma_kernel<<<dim3(H, B, 2), 256, conv_smem>>>(bm, gam, bet, mean, var, out);
}

// round 17
// speedup vs baseline: 1.0785x; 1.0785x over previous
#include <cuda_runtime.h>
#include <cuda_fp16.h>
#include <cstdint>

// Problem constants
constexpr int C   = 64;
constexpr int H   = 128;
constexpr int W   = 128;
constexpr int HW  = 16384;
constexpr int B   = 8;
constexpr int C3  = 192;

// ---------------------------------------------------------------------------
// Scratch (device globals).
// x1/x2 keep hi+lo (attn GEMM1 A-side 2-term); xf/xr/xpt are hi-only
// (validated error model: each dropped residual term ~2e-4 in quadrature).
// ---------------------------------------------------------------------------
__device__ __half g_x1h[(size_t)B * H * C * W], g_x1l[(size_t)B * H * C * W];
__device__ __half g_x2h[(size_t)B * H * C * W], g_x2l[(size_t)B * H * C * W];
__device__ __half g_xfh[(size_t)B * H * C * W];
__device__ __half g_xrh[(size_t)B * H * C * W];
__device__ __half g_xpth[(size_t)B * H * W * C];
__device__ __half g_inh[(size_t)B * H * W * C3];
__device__ __half g_wh16[54 * 192 * 32];

// ---------------------------------------------------------------------------
// Helpers
// ---------------------------------------------------------------------------
__device__ __forceinline__ void cpa16(void* dst, const void* src) {
    uint32_t d = (uint32_t)__cvta_generic_to_shared(dst);
    asm volatile("cp.async.cg.shared.global [%0], [%1], 16;" :: "r"(d), "l"(src));
}
#define CP_COMMIT() asm volatile("cp.async.commit_group;" ::: "memory")
#define CP_WAIT2()  asm volatile("cp.async.wait_group 2;" ::: "memory")

__device__ __forceinline__ void mma16816(float acc[4], uint32_t a0, uint32_t a1,
                                         uint32_t a2, uint32_t a3,
                                         uint32_t b0, uint32_t b1) {
    asm volatile(
        "mma.sync.aligned.m16n8k16.row.col.f32.f16.f16.f32 "
        "{%0,%1,%2,%3}, {%4,%5,%6,%7}, {%8,%9}, {%0,%1,%2,%3};"
        : "+f"(acc[0]), "+f"(acc[1]), "+f"(acc[2]), "+f"(acc[3])
        : "r"(a0), "r"(a1), "r"(a2), "r"(a3), "r"(b0), "r"(b1));
}

__device__ __forceinline__ void ldsm4(uint32_t& r0, uint32_t& r1, uint32_t& r2,
                                      uint32_t& r3, const __half* p) {
    uint32_t a = (uint32_t)__cvta_generic_to_shared(p);
    asm volatile("ldmatrix.sync.aligned.m8n8.x4.shared.b16 {%0,%1,%2,%3}, [%4];"
                 : "=r"(r0), "=r"(r1), "=r"(r2), "=r"(r3) : "r"(a));
}

__device__ __forceinline__ void split16(float v, __half& hi, __half& lo) {
    hi = __float2half_rn(v);
    lo = __float2half_rn(v - __half2float(hi));
}

// ---------------------------------------------------------------------------
// Kernel 1: tensor-core pointwise projections (3-term fp16 split internally).
// Outputs: x1/x2 hi+lo; xfp/xrp hi only; xp transposed hi only.
// ---------------------------------------------------------------------------

#define PJS 72
#define PO_WH  0
#define PO_WL  4608
#define PO_INH 9216
#define PO_INL 18432
#define PO_TMP 27648            // fp32 [64][129] staging (16512 halfs)
#define PROJ_SMEM_HALFS (27648 + 16512)

__global__ __launch_bounds__(256, 2) void proj_mma_kernel(
    const float* __restrict__ x, const float* __restrict__ xf, const float* __restrict__ xr,
    const float* __restrict__ Wx,  const float* __restrict__ bx,
    const float* __restrict__ Wx1, const float* __restrict__ bx1,
    const float* __restrict__ Wx2, const float* __restrict__ bx2,
    const float* __restrict__ Wxf, const float* __restrict__ bxf,
    const float* __restrict__ Wxr, const float* __restrict__ bxr) {
    extern __shared__ __align__(16) __half smh[];
    __half* sWh  = smh + PO_WH;
    __half* sWl  = smh + PO_WL;
    __half* sInH = smh + PO_INH;
    __half* sInL = smh + PO_INL;
    float*  sTmp = (float*)(smh + PO_TMP);   // [64][129]

    const int tid = threadIdx.x;
    const int b   = blockIdx.x >> 7;
    const int h   = blockIdx.x & 127;
    const size_t bh = (size_t)b * 128 + h;
    const size_t gbase = (size_t)b * C * HW + (size_t)h * W;

    const int lane = tid & 31;
    const int wid = tid >> 5;
    const int lr = lane >> 2;
    const int lc2 = (lane & 3) * 2;
    const int grp = lane >> 3;
    const int gr  = lane & 7;
    const int aoffW = ((grp & 1) * 8 + gr) * PJS + (grp >> 1) * 8;
    const int boffI = ((grp >> 1) * 8 + gr) * PJS + (grp & 1) * 8;
    const int m0 = (wid & 1) * 32;
    const int n0 = (wid >> 1) * 32;

    auto loadW = [&](const float* Wg) {
        for (int i = tid; i < 4096; i += 256) {
            int o = i >> 6, c = i & 63;
            __half hi, lo;
            split16(Wg[i], hi, lo);
            sWh[o * PJS + c] = hi;
            sWl[o * PJS + c] = lo;
        }
    };
    auto loadTmp = [&](const float* src) {
        for (int i = tid; i < 8192; i += 256) {
            int c = i >> 7, p = i & 127;
            sTmp[c * 129 + p] = src[gbase + (size_t)c * HW + p];
        }
    };
    auto transSplit = [&]() {
        for (int i = tid; i < 8192; i += 256) {
            int c = i & 63, w = i >> 6;
            __half hi, lo;
            split16(sTmp[c * 129 + w], hi, lo);
            sInH[w * PJS + c] = hi;
            sInL[w * PJS + c] = lo;
        }
    };

    float acc[2][4][4];
    auto gemm3 = [&]() {
#pragma unroll
        for (int mt = 0; mt < 2; mt++)
#pragma unroll
            for (int nf = 0; nf < 4; nf++)
#pragma unroll
                for (int i = 0; i < 4; i++) acc[mt][nf][i] = 0.f;
#pragma unroll
        for (int ks = 0; ks < 4; ks++) {
            const int k0 = ks * 16;
            uint32_t bhf[4][2], blf[4][2];
#pragma unroll
            for (int ntp = 0; ntp < 2; ntp++) {
                const int nb = (n0 + ntp * 16) * PJS + k0 + boffI;
                ldsm4(bhf[ntp * 2][0], bhf[ntp * 2][1], bhf[ntp * 2 + 1][0],
                      bhf[ntp * 2 + 1][1], sInH + nb);
                ldsm4(blf[ntp * 2][0], blf[ntp * 2][1], blf[ntp * 2 + 1][0],
                      blf[ntp * 2 + 1][1], sInL + nb);
            }
#pragma unroll
            for (int mt = 0; mt < 2; mt++) {
                const int mb = (m0 + mt * 16) * PJS + k0 + aoffW;
                uint32_t ah0, ah1, ah2, ah3, al0, al1, al2, al3;
                ldsm4(ah0, ah1, ah2, ah3, sWh + mb);
                ldsm4(al0, al1, al2, al3, sWl + mb);
#pragma unroll
                for (int nf = 0; nf < 4; nf++)
                    mma16816(acc[mt][nf], ah0, ah1, ah2, ah3, bhf[nf][0], bhf[nf][1]);
#pragma unroll
                for (int nf = 0; nf < 4; nf++)
                    mma16816(acc[mt][nf], al0, al1, al2, al3, bhf[nf][0], bhf[nf][1]);
#pragma unroll
                for (int nf = 0; nf < 4; nf++)
                    mma16816(acc[mt][nf], ah0, ah1, ah2, ah3, blf[nf][0], blf[nf][1]);
            }
        }
    };

    // split store (x1/x2)
    auto storeCW = [&](const float* bias, __half* dh, __half* dl) {
#pragma unroll
        for (int mt = 0; mt < 2; mt++) {
            const int ob = m0 + mt * 16 + lr;
            const float b0 = __ldg(bias + ob);
            const float b1 = __ldg(bias + ob + 8);
#pragma unroll
            for (int nf = 0; nf < 4; nf++) {
                const int wcol = n0 + nf * 8 + lc2;
                __half h0, l0, h1, l1;
                split16(acc[mt][nf][0] + b0, h0, l0);
                split16(acc[mt][nf][1] + b0, h1, l1);
                size_t rb = (bh * 64 + ob) * 128 + wcol;
                *(__half2*)(dh + rb) = __halves2half2(h0, h1);
                *(__half2*)(dl + rb) = __halves2half2(l0, l1);
                split16(acc[mt][nf][2] + b1, h0, l0);
                split16(acc[mt][nf][3] + b1, h1, l1);
                rb += (size_t)8 * 128;
                *(__half2*)(dh + rb) = __halves2half2(h0, h1);
                *(__half2*)(dl + rb) = __halves2half2(l0, l1);
            }
        }
    };
    // hi-only store (xfp/xrp)
    auto storeCWhi = [&](const float* bias, __half* dh) {
#pragma unroll
        for (int mt = 0; mt < 2; mt++) {
            const int ob = m0 + mt * 16 + lr;
            const float b0 = __ldg(bias + ob);
            const float b1 = __ldg(bias + ob + 8);
#pragma unroll
            for (int nf = 0; nf < 4; nf++) {
                const int wcol = n0 + nf * 8 + lc2;
                size_t rb = (bh * 64 + ob) * 128 + wcol;
                *(__half2*)(dh + rb) =
                    __halves2half2(__float2half_rn(acc[mt][nf][0] + b0),
                                   __float2half_rn(acc[mt][nf][1] + b0));
                rb += (size_t)8 * 128;
                *(__half2*)(dh + rb) =
                    __halves2half2(__float2half_rn(acc[mt][nf][2] + b1),
                                   __float2half_rn(acc[mt][nf][3] + b1));
            }
        }
    };

    // ---- xp chain ----
    loadTmp(x);
    __syncthreads();
    transSplit();
    loadW(Wx);
    __syncthreads();
    gemm3();
    __syncthreads();
    // xp (+bias) -> sIn transposed [w][c] (hi+lo kept: x1/x2 GEMM inputs)
    {
#pragma unroll
        for (int mt = 0; mt < 2; mt++) {
            const int ob = m0 + mt * 16 + lr;
            const float b0 = __ldg(bx + ob);
            const float b1 = __ldg(bx + ob + 8);
#pragma unroll
            for (int nf = 0; nf < 4; nf++) {
#pragma unroll
                for (int i = 0; i < 4; i++) {
                    int o = ob + ((i & 2) ? 8 : 0);
                    int w = n0 + nf * 8 + lc2 + (i & 1);
                    __half hi, lo;
                    split16(acc[mt][nf][i] + ((i & 2) ? b1 : b0), hi, lo);
                    sInH[w * PJS + o] = hi;
                    sInL[w * PJS + o] = lo;
                }
            }
        }
    }
    loadW(Wx1);
    __syncthreads();
    // dump xpt (hi only) + x1 GEMM
    {
        __half* gh = g_xpth + bh * 128 * 64;
        for (int i = tid; i < 1024; i += 256) {
            int r = i >> 3, g = i & 7;
            *(uint4*)(gh + r * 64 + g * 8) = *(const uint4*)(sInH + r * PJS + g * 8);
        }
    }
    gemm3();
    storeCW(bx1, g_x1h, g_x1l);
    __syncthreads();
    loadW(Wx2);
    loadTmp(xf);
    __syncthreads();
    gemm3();
    storeCW(bx2, g_x2h, g_x2l);
    __syncthreads();
    // ---- xfp (hi only out) ----
    transSplit();
    loadW(Wxf);
    __syncthreads();
    gemm3();
    storeCWhi(bxf, g_xfh);
    loadTmp(xr);
    __syncthreads();
    // ---- xrp (hi only out) ----
    transSplit();
    loadW(Wxr);
    __syncthreads();
    gemm3();
    storeCWhi(bxr, g_xrh);
}

// ---------------------------------------------------------------------------
// Kernel 2: tensor-core attention + conv-input packing.
// GEMM1 2-term: x1h·xfh + x1l·xfh.  GEMM2 2-term: sh·ph + sl·ph.
// smem 69KB -> 3 CTAs/SM. Score aliases dead x1 region; feat fp32 staging
// aliases dead x1l/xf region.
// ---------------------------------------------------------------------------

#define AS1 136   // x1h/x1l/xfh tile stride (64 rows x 128 K)
#define ASP 72    // xpt tile stride (128 rows x 64 K)
#define ASS 72    // score stride (64 rows x 64 K)
#define ASF 129   // feat fp32 staging stride (floats)
#define O_X1H 0
#define O_X1L 8704
#define O_XFH 17408
#define O_PH  26112
#define ATTN_SMEM_HALFS 35328   // 70656 bytes

__global__ __launch_bounds__(256, 3) void attn_mma_kernel(const float* __restrict__ x) {
    extern __shared__ __align__(16) __half smh[];
    __half* sX1h = smh + O_X1H;
    __half* sX1l = smh + O_X1L;
    __half* sXfh = smh + O_XFH;
    __half* sPh  = smh + O_PH;
    __half* sSh  = smh;                    // alias over dead x1h (after GEMM1)
    __half* sSl  = smh + 4608;             // alias over x1h tail / x1l head
    float*  sF   = (float*)(smh + 9216);   // 8256 floats over x1l tail + xfh

    const int tid = threadIdx.x;
    const int h = blockIdx.x, b = blockIdx.y;
    const size_t bh = (size_t)b * 128 + h;

    const int lane = tid & 31;
    const int wid = tid >> 5;
    const int lr = lane >> 2;
    const int lc2 = (lane & 3) * 2;
    const int grp = lane >> 3;
    const int gr  = lane & 7;

    uint32_t* outh = (uint32_t*)g_inh;
    const size_t wbase = bh * 128 * 96;

    // ---- load xpt (hi only) ----
    {
        const __half* srcH = g_xpth + bh * 128 * 64;
        for (int idx = tid; idx < 1024; idx += 256) {
            int r = idx >> 3, g = idx & 7;
            *(uint4*)(sPh + r * ASP + g * 8) = *(const uint4*)(srcH + r * 64 + g * 8);
        }
    }
    // ---- pack x (channels 128..191) ----
    {
        const size_t xbase = (size_t)b * C * HW + (size_t)h * W;
        for (int idx = tid; idx < 8192; idx += 256) {
            int c = idx >> 7, w = idx & 127;
            sF[c * ASF + w] = x[xbase + (size_t)c * HW + w];
        }
        __syncthreads();
        for (int idx = tid; idx < 4096; idx += 256) {
            int q = idx & 31, w = idx >> 5;
            int c = q * 2;
            __half2 ph = __halves2half2(__float2half_rn(sF[c * ASF + w]),
                                        __float2half_rn(sF[(c + 1) * ASF + w]));
            outh[wbase + (size_t)w * 96 + 64 + q] = *(uint32_t*)&ph;
        }
    }

    const int aoff1 = ((grp & 1) * 8 + gr) * AS1 + (grp >> 1) * 8;
    const int boff1 = ((grp >> 1) * 8 + gr) * AS1 + (grp & 1) * 8;
    const int aoffS = ((grp & 1) * 8 + gr) * ASS + (grp >> 1) * 8;
    const int boffP = ((grp >> 1) * 8 + gr) * ASP + (grp & 1) * 8;

    for (int pass = 0; pass < 2; pass++) {
        const __half* gAh = pass ? g_x2h : g_x1h;
        const __half* gAl = pass ? g_x2l : g_x1l;
        const __half* gBh = pass ? g_xrh : g_xfh;

        __syncthreads();   // previous pass reads done before overwriting tiles
        {
            const size_t sb = bh * 64 * 128;
            for (int idx = tid; idx < 1024; idx += 256) {
                int r = idx >> 4, g = idx & 15;
                *(uint4*)(sX1h + r * AS1 + g * 8) = *(const uint4*)(gAh + sb + r * 128 + g * 8);
                *(uint4*)(sX1l + r * AS1 + g * 8) = *(const uint4*)(gAl + sb + r * 128 + g * 8);
                *(uint4*)(sXfh + r * AS1 + g * 8) = *(const uint4*)(gBh + sb + r * 128 + g * 8);
            }
        }
        __syncthreads();

        // ---- GEMM1 (2-term): score = (x1h + x1l) @ xfh^T ----
        float sacc[4][4];
#pragma unroll
        for (int nf = 0; nf < 4; nf++)
#pragma unroll
            for (int i = 0; i < 4; i++) sacc[nf][i] = 0.f;
        {
            const int m0 = (wid & 3) * 16, n0 = (wid >> 2) * 32;
#pragma unroll
            for (int ks = 0; ks < 8; ks++) {
                const int k0 = ks * 16;
                uint32_t bhf[4][2];
#pragma unroll
                for (int ntp = 0; ntp < 2; ntp++) {
                    const int nb = (n0 + ntp * 16) * AS1 + k0 + boff1;
                    ldsm4(bhf[ntp * 2][0], bhf[ntp * 2][1], bhf[ntp * 2 + 1][0],
                          bhf[ntp * 2 + 1][1], sXfh + nb);
                }
                const int mb = m0 * AS1 + k0 + aoff1;
                uint32_t ah0, ah1, ah2, ah3, al0, al1, al2, al3;
                ldsm4(ah0, ah1, ah2, ah3, sX1h + mb);
                ldsm4(al0, al1, al2, al3, sX1l + mb);
#pragma unroll
                for (int nf = 0; nf < 4; nf++)
                    mma16816(sacc[nf], ah0, ah1, ah2, ah3, bhf[nf][0], bhf[nf][1]);
#pragma unroll
                for (int nf = 0; nf < 4; nf++)
                    mma16816(sacc[nf], al0, al1, al2, al3, bhf[nf][0], bhf[nf][1]);
            }
        }
        __syncthreads();   // GEMM1 done -> x1/xf dead; score may alias

        // ---- score -> smem split fp16 ----
        {
            const int m0 = (wid & 3) * 16, n0 = (wid >> 2) * 32;
#pragma unroll
            for (int nf = 0; nf < 4; nf++)
#pragma unroll
                for (int i = 0; i < 4; i++) {
                    int row = m0 + lr + (i >= 2 ? 8 : 0);
                    int col = n0 + nf * 8 + lc2 + (i & 1);
                    __half hi, lo;
                    split16(sacc[nf][i], hi, lo);
                    sSh[row * ASS + col] = hi;
                    sSl[row * ASS + col] = lo;
                }
        }
        __syncthreads();

        // ---- GEMM2 (2-term): feat = (sh + sl) @ ph ----
        float facc[2][4][4];
#pragma unroll
        for (int mt = 0; mt < 2; mt++)
#pragma unroll
            for (int nf = 0; nf < 4; nf++)
#pragma unroll
                for (int i = 0; i < 4; i++) facc[mt][nf][i] = 0.f;
        {
            const int m0 = (wid & 1) * 32, n0 = (wid >> 1) * 32;
#pragma unroll
            for (int ks = 0; ks < 4; ks++) {
                const int k0 = ks * 16;
                uint32_t bhf[4][2];
#pragma unroll
                for (int ntp = 0; ntp < 2; ntp++) {
                    const int nb = (n0 + ntp * 16) * ASP + k0 + boffP;
                    ldsm4(bhf[ntp * 2][0], bhf[ntp * 2][1], bhf[ntp * 2 + 1][0],
                          bhf[ntp * 2 + 1][1], sPh + nb);
                }
#pragma unroll
                for (int mt = 0; mt < 2; mt++) {
                    const int mb = (m0 + mt * 16) * ASS + k0 + aoffS;
                    uint32_t ah0, ah1, ah2, ah3, al0, al1, al2, al3;
                    ldsm4(ah0, ah1, ah2, ah3, sSh + mb);
                    ldsm4(al0, al1, al2, al3, sSl + mb);
#pragma unroll
                    for (int nf = 0; nf < 4; nf++)
                        mma16816(facc[mt][nf], ah0, ah1, ah2, ah3, bhf[nf][0], bhf[nf][1]);
#pragma unroll
                    for (int nf = 0; nf < 4; nf++)
                        mma16816(facc[mt][nf], al0, al1, al2, al3, bhf[nf][0], bhf[nf][1]);
                }
            }
        }
        // feat fp32 -> sF (disjoint from score & xpt regions)
        {
            const int m0 = (wid & 1) * 32, n0 = (wid >> 1) * 32;
#pragma unroll
            for (int mt = 0; mt < 2; mt++)
#pragma unroll
                for (int nf = 0; nf < 4; nf++)
#pragma unroll
                    for (int i = 0; i < 4; i++) {
                        int row = m0 + mt * 16 + lr + (i >= 2 ? 8 : 0);
                        int col = n0 + nf * 8 + lc2 + (i & 1);
                        sF[row * ASF + col] = facc[mt][nf][i];
                    }
        }
        __syncthreads();

        // ---- pack feat (channels pass*64 ..) ----
        for (int idx = tid; idx < 4096; idx += 256) {
            int q = idx & 31, w = idx >> 5;
            int c = q * 2;
            __half2 ph = __halves2half2(__float2half_rn(sF[c * ASF + w]),
                                        __float2half_rn(sF[(c + 1) * ASF + w]));
            outh[wbase + (size_t)w * 96 + pass * 32 + q] = *(uint32_t*)&ph;
        }
    }
}

// ---------------------------------------------------------------------------
// Kernel 3a: weight prep (fp16).
// ---------------------------------------------------------------------------
__global__ void wprep_kernel(const float* __restrict__ Wm) {
    const int kc = blockIdx.x;       // 0..53
    const int o  = threadIdx.x;      // 0..191
    const int tap = kc / 6;
    const int ch0 = (kc - tap * 6) * 32;
#pragma unroll
    for (int j = 0; j < 32; j++) {
        float v  = Wm[((size_t)o * 192 + ch0 + j) * 9 + tap];
        g_wh16[((size_t)kc * 192 + o) * 32 + j] = __float2half_rn(v);
    }
}

// ---------------------------------------------------------------------------
// Kernel 3b: pure fp16 mma.sync implicit-GEMM conv + BN + ReLU.
// (R12 version — at the HMMA throughput ceiling; do not touch.)
// ---------------------------------------------------------------------------

#define AST 40
#define A_TILE (192 * AST)
#define B_TILE (128 * AST)
#define CONV_SMEM_BYTES ((4 * A_TILE + 4 * B_TILE) * 2 + 384 * 4)

__global__ __launch_bounds__(256, 2) void conv_mma_kernel(
    const float* __restrict__ bm, const float* __restrict__ gamma,
    const float* __restrict__ beta, const float* __restrict__ mean,
    const float* __restrict__ var, float* __restrict__ out) {
    extern __shared__ __align__(16) __half smh[];
    __half* sAh = smh;                        // [4][A_TILE]
    __half* sBh = sAh + 4 * A_TILE;           // [4][B_TILE]
    float* ssc = (float*)(sBh + 4 * B_TILE);
    float* sbi = ssc + 192;

    const int tid = threadIdx.x;
    const int h = blockIdx.x, b = blockIdx.y;

    if (tid < 192) {
        float scv = gamma[tid] * rsqrtf(var[tid] + 1e-4f);
        ssc[tid] = scv;
        sbi[tid] = (bm[tid] - mean[tid]) * scv + beta[tid];
    }

    const int lane = tid & 31;
    const int wid = tid >> 5;
    const int wm = wid & 1;
    const int wn = wid >> 1;
    const int lr = lane >> 2;
    const int lc2 = (lane & 3) * 2;
    const int grp = lane >> 3;
    const int gr  = lane & 7;
    const int aoff = ((grp & 1) * 8 + gr) * AST + (grp >> 1) * 8;
    const int boff = ((grp >> 1) * 8 + gr) * AST + (grp & 1) * 8;

    float acc[6][4][4];
#pragma unroll
    for (int mt = 0; mt < 6; mt++)
#pragma unroll
        for (int nt = 0; nt < 4; nt++)
#pragma unroll
            for (int i = 0; i < 4; i++) acc[mt][nt][i] = 0.f;

    auto stage = [&](int kc, int buf) {
        const int tap = kc / 6;
        const int ch0 = (kc - tap * 6) * 32;
        const int dh = tap / 3 - 1;
        const int dw = tap - (tap / 3) * 3 - 1;
        const int row = h + dh;
        const bool rok = ((unsigned)row < 128u);
        const __half* wh = g_wh16 + (size_t)kc * 6144;
#pragma unroll
        for (int i = 0; i < 3; i++) {
            int idx = tid + i * 256;
            int r = idx >> 2, g = idx & 3;
            cpa16(sAh + buf * A_TILE + r * AST + g * 8, wh + r * 32 + g * 8);
        }
        const size_t rowbase = ((size_t)(b * 128 + row) * 128) * 192;
#pragma unroll
        for (int i = 0; i < 2; i++) {
            int idx = tid + i * 256;
            int r = idx >> 2, g = idx & 3;
            int wsrc = r + dw;
            bool ok = rok && ((unsigned)wsrc < 128u);
            __half* dh_ = sBh + buf * B_TILE + r * AST + g * 8;
            if (ok) {
                cpa16(dh_, g_inh + rowbase + (size_t)wsrc * 192 + ch0 + g * 8);
            } else {
                *(uint4*)dh_ = make_uint4(0, 0, 0, 0);
            }
        }
    };

    stage(0, 0); CP_COMMIT();
    stage(1, 1); CP_COMMIT();
    stage(2, 2); CP_COMMIT();

    for (int kc = 0; kc < 54; kc++) {
        const int buf = kc & 3;
        CP_WAIT2();
        __syncthreads();
        if (kc + 3 < 54) stage(kc + 3, (kc + 3) & 3);
        CP_COMMIT();

        const __half* bAh = sAh + buf * A_TILE;
        const __half* bBh = sBh + buf * B_TILE;

#pragma unroll
        for (int ks = 0; ks < 2; ks++) {
            const int kk = ks * 16;
            uint32_t bh[4][2];
#pragma unroll
            for (int ntp = 0; ntp < 2; ntp++) {
                const int nb = (wn * 32 + ntp * 16) * AST + kk + boff;
                ldsm4(bh[ntp * 2][0], bh[ntp * 2][1], bh[ntp * 2 + 1][0],
                      bh[ntp * 2 + 1][1], bBh + nb);
            }
#pragma unroll
            for (int mt = 0; mt < 6; mt++) {
                const int mb = (wm * 96 + mt * 16) * AST + kk + aoff;
                uint32_t ah0, ah1, ah2, ah3;
                ldsm4(ah0, ah1, ah2, ah3, bAh + mb);
#pragma unroll
                for (int nt = 0; nt < 4; nt++)
                    mma16816(acc[mt][nt], ah0, ah1, ah2, ah3, bh[nt][0], bh[nt][1]);
            }
        }
    }

#pragma unroll
    for (int mt = 0; mt < 6; mt++) {
        int o0 = wm * 96 + mt * 16 + lr;
        float s0 = ssc[o0],     bi0 = sbi[o0];
        float s1 = ssc[o0 + 8], bi1 = sbi[o0 + 8];
#pragma unroll
        for (int nt = 0; nt < 4; nt++) {
            int wcol = wn * 32 + nt * 8 + lc2;
            float2 v0, v1;
            v0.x = fmaxf(acc[mt][nt][0] * s0 + bi0, 0.f);
            v0.y = fmaxf(acc[mt][nt][1] * s0 + bi0, 0.f);
            v1.x = fmaxf(acc[mt][nt][2] * s1 + bi1, 0.f);
            v1.y = fmaxf(acc[mt][nt][3] * s1 + bi1, 0.f);
            size_t p0 = (((size_t)b * C3 + o0)     * H + h) * W + wcol;
            size_t p1 = (((size_t)b * C3 + o0 + 8) * H + h) * W + wcol;
            *(float2*)(out + p0) = v0;
            *(float2*)(out + p1) = v1;
        }
    }
}

// ---------------------------------------------------------------------------

extern "C" void kernel_launch(void* const* d_in, const int* in_sizes, int n_in,
                              void* d_out, int out_size) {
    const float* x    = (const float*)d_in[0];
    const float* xf   = (const float*)d_in[1];
    const float* xr   = (const float*)d_in[2];
    const float* Wx   = (const float*)d_in[3];
    const float* bx   = (const float*)d_in[4];
    const float* Wx1  = (const float*)d_in[5];
    const float* bx1  = (const float*)d_in[6];
    const float* Wx2  = (const float*)d_in[7];
    const float* bx2  = (const float*)d_in[8];
    const float* Wxf  = (const float*)d_in[9];
    const float* bxf  = (const float*)d_in[10];
    const float* Wxr  = (const float*)d_in[11];
    const float* bxr  = (const float*)d_in[12];
    const float* Wm   = (const float*)d_in[13];
    const float* bm   = (const float*)d_in[14];
    const float* gam  = (const float*)d_in[15];
    const float* bet  = (const float*)d_in[16];
    const float* mean = (const float*)d_in[17];
    const float* var  = (const float*)d_in[18];
    float* out = (float*)d_out;

    const int proj_smem = PROJ_SMEM_HALFS * 2;
    const int attn_smem = ATTN_SMEM_HALFS * 2;
    const int conv_smem = CONV_SMEM_BYTES;
    cudaFuncSetAttribute(proj_mma_kernel, cudaFuncAttributeMaxDynamicSharedMemorySize, proj_smem);
    cudaFuncSetAttribute(attn_mma_kernel, cudaFuncAttributeMaxDynamicSharedMemorySize, attn_smem);
    cudaFuncSetAttribute(conv_mma_kernel, cudaFuncAttributeMaxDynamicSharedMemorySize, conv_smem);

    proj_mma_kernel<<<B * H, 256, proj_smem>>>(x, xf, xr, Wx, bx, Wx1, bx1,
                                               Wx2, bx2, Wxf, bxf, Wxr, bxr);
    wprep_kernel<<<54, 192>>>(Wm);
    attn_mma_kernel<<<dim3(H, B), 256, attn_smem>>>(x);
    conv_mma_kernel<<<dim3(H, B), 256, conv_smem>>>(bm, gam, bet, mean, var, out);
}